// round 2
// baseline (speedup 1.0000x reference)
#include <cuda_runtime.h>
#include <cuda_bf16.h>
#include <math.h>

#define N_NODES 50000
#define N_EDGES 800000
#define IN_SIZE 256
#define OUT_SIZE 128
#define EDGE_DIM 64

// ---------------- scratch (static device globals; no runtime allocation) ----
__device__ float g_q[(size_t)N_NODES * OUT_SIZE];
__device__ float g_k[(size_t)N_NODES * OUT_SIZE];
__device__ float g_v[(size_t)N_NODES * OUT_SIZE];
__device__ float g_skip[(size_t)N_NODES * OUT_SIZE];
__device__ float g_e[(size_t)N_EDGES * OUT_SIZE];
__device__ int   g_deg[N_NODES];
__device__ int   g_off[N_NODES + 1];
__device__ int   g_cur[N_NODES];
__device__ int   g_eorder[N_EDGES];

__device__ __forceinline__ int clamp_node(int v) {
    return (v < 0) ? 0 : ((v >= N_NODES) ? N_NODES - 1 : v);
}

// ---------------- SGEMM: C[M,N] = A[M,K] @ B[K,N] + bias[N] -----------------
// BM=128 BN=128 BK=8, 256 threads, 8x8 per-thread tile.
template <int BM, int BN, int BK, int TM, int TN>
__global__ __launch_bounds__(256) void sgemm_bias(
    const float* __restrict__ A, const float* __restrict__ B,
    const float* __restrict__ bias, float* __restrict__ C,
    int M, int N, int K)
{
    __shared__ float As[BK][BM];
    __shared__ float Bs[BK][BN];

    const int tid  = threadIdx.x;
    const int row0 = blockIdx.y * BM;
    const int col0 = blockIdx.x * BN;

    const int tRow = (tid / (BN / TN)) * TM;
    const int tCol = (tid % (BN / TN)) * TN;

    const int aRow = tid / (BK / 4);
    const int aCol = (tid % (BK / 4)) * 4;
    const int bRow = tid / (BN / 4);
    const int bCol = (tid % (BN / 4)) * 4;

    float acc[TM][TN];
#pragma unroll
    for (int i = 0; i < TM; i++)
#pragma unroll
        for (int j = 0; j < TN; j++) acc[i][j] = 0.0f;

    for (int k0 = 0; k0 < K; k0 += BK) {
        float4 av = make_float4(0.f, 0.f, 0.f, 0.f);
        if (row0 + aRow < M)
            av = *(const float4*)(A + (size_t)(row0 + aRow) * K + k0 + aCol);
        As[aCol + 0][aRow] = av.x;
        As[aCol + 1][aRow] = av.y;
        As[aCol + 2][aRow] = av.z;
        As[aCol + 3][aRow] = av.w;

        float4 bv = *(const float4*)(B + (size_t)(k0 + bRow) * N + col0 + bCol);
        *(float4*)&Bs[bRow][bCol] = bv;

        __syncthreads();

        float regM[TM], regN[TN];
#pragma unroll
        for (int kk = 0; kk < BK; kk++) {
#pragma unroll
            for (int i = 0; i < TM; i++) regM[i] = As[kk][tRow + i];
#pragma unroll
            for (int j = 0; j < TN; j++) regN[j] = Bs[kk][tCol + j];
#pragma unroll
            for (int i = 0; i < TM; i++)
#pragma unroll
                for (int j = 0; j < TN; j++)
                    acc[i][j] = fmaf(regM[i], regN[j], acc[i][j]);
        }
        __syncthreads();
    }

#pragma unroll
    for (int i = 0; i < TM; i++) {
        int r = row0 + tRow + i;
        if (r >= M) continue;
#pragma unroll
        for (int j = 0; j < TN; j += 4) {
            int c = col0 + tCol + j;
            float4 o;
            o.x = acc[i][j + 0] + bias[c + 0];
            o.y = acc[i][j + 1] + bias[c + 1];
            o.z = acc[i][j + 2] + bias[c + 2];
            o.w = acc[i][j + 3] + bias[c + 3];
            *(float4*)(C + (size_t)r * N + c) = o;
        }
    }
}

// ---------------- CSR build ---------------------------------------------
__global__ void zero_deg_kernel() {
    int i = blockIdx.x * blockDim.x + threadIdx.x;
    if (i < N_NODES) g_deg[i] = 0;
}

__global__ void count_kernel(const int* __restrict__ edge_index) {
    int i = blockIdx.x * blockDim.x + threadIdx.x;
    if (i < N_EDGES) {
        int dst = clamp_node(edge_index[N_EDGES + i]);
        atomicAdd(&g_deg[dst], 1);
    }
}

// single-block exclusive scan over 50000 degrees
__global__ void scan_kernel() {
    __shared__ int sums[1024];
    const int CH = (N_NODES + 1023) / 1024;   // 49
    int t = threadIdx.x;
    int base = t * CH;
    int sum = 0;
    for (int j = 0; j < CH; j++) {
        int idx = base + j;
        if (idx < N_NODES) sum += g_deg[idx];
    }
    sums[t] = sum;
    __syncthreads();
    for (int off = 1; off < 1024; off *= 2) {
        int v = (t >= off) ? sums[t - off] : 0;
        __syncthreads();
        sums[t] += v;
        __syncthreads();
    }
    int run = (t == 0) ? 0 : sums[t - 1];
    for (int j = 0; j < CH; j++) {
        int idx = base + j;
        if (idx < N_NODES) {
            g_off[idx] = run;
            g_cur[idx] = run;
            run += g_deg[idx];
        }
    }
    if (t == 1023) g_off[N_NODES] = run;
}

__global__ void scatter_kernel(const int* __restrict__ edge_index) {
    int i = blockIdx.x * blockDim.x + threadIdx.x;
    if (i < N_EDGES) {
        int dst = clamp_node(edge_index[N_EDGES + i]);
        int p = atomicAdd(&g_cur[dst], 1);
        if (p >= 0 && p < N_EDGES) g_eorder[p] = i;
    }
}

// ---------------- fused attention + aggregate + skip + ELU -------------------
// one warp per destination node; online softmax; no float atomics.
__global__ __launch_bounds__(256) void attn_kernel(
    const int* __restrict__ edge_index, float* __restrict__ out)
{
    const int warp = threadIdx.x / 32;
    const int lane = threadIdx.x % 32;
    const int node = blockIdx.x * 8 + warp;
    if (node >= N_NODES) return;

    const float4 qv = *(const float4*)(g_q + (size_t)node * OUT_SIZE + lane * 4);

    float4 acc = make_float4(0.f, 0.f, 0.f, 0.f);
    float m = -INFINITY;
    float s = 0.f;

    int beg = g_off[node];
    int end = g_off[node + 1];
    // defensive clamps: never loop out of range even if offsets were corrupted
    if (beg < 0) beg = 0;
    if (end > N_EDGES) end = N_EDGES;

    for (int p = beg; p < end; p++) {
        const int ei  = g_eorder[p];
        const int src = clamp_node(__ldg(&edge_index[ei]));

        const float4 ev = *(const float4*)(g_e + (size_t)ei  * OUT_SIZE + lane * 4);
        const float4 kv = *(const float4*)(g_k + (size_t)src * OUT_SIZE + lane * 4);
        const float4 vv = *(const float4*)(g_v + (size_t)src * OUT_SIZE + lane * 4);

        float d = fmaf(qv.x, kv.x + ev.x,
                  fmaf(qv.y, kv.y + ev.y,
                  fmaf(qv.z, kv.z + ev.z,
                       qv.w * (kv.w + ev.w))));
#pragma unroll
        for (int off = 16; off > 0; off >>= 1)
            d += __shfl_xor_sync(0xFFFFFFFFu, d, off);

        const float alpha = d * 0.08838834764831845f;   // 1/sqrt(128)
        const float nm = fmaxf(m, alpha);
        const float f  = __expf(m - nm);      // 0 on first edge (m = -inf)
        const float w  = __expf(alpha - nm);
        s = s * f + w;
        acc.x = fmaf(w, vv.x + ev.x, acc.x * f);
        acc.y = fmaf(w, vv.y + ev.y, acc.y * f);
        acc.z = fmaf(w, vv.z + ev.z, acc.z * f);
        acc.w = fmaf(w, vv.w + ev.w, acc.w * f);
        m = nm;
    }

    const float inv = 1.0f / (s + 1e-16f);
    const float4 sk = *(const float4*)(g_skip + (size_t)node * OUT_SIZE + lane * 4);

    float4 o;
    o.x = fmaf(acc.x, inv, sk.x);
    o.y = fmaf(acc.y, inv, sk.y);
    o.z = fmaf(acc.z, inv, sk.z);
    o.w = fmaf(acc.w, inv, sk.w);

    // ELU
    o.x = (o.x > 0.f) ? o.x : expm1f(o.x);
    o.y = (o.y > 0.f) ? o.y : expm1f(o.y);
    o.z = (o.z > 0.f) ? o.z : expm1f(o.z);
    o.w = (o.w > 0.f) ? o.w : expm1f(o.w);

    *(float4*)(out + (size_t)node * OUT_SIZE + lane * 4) = o;
}

// ---------------- launch -----------------------------------------------------
extern "C" void kernel_launch(void* const* d_in, const int* in_sizes, int n_in,
                              void* d_out, int out_size)
{
    const float* x    = (const float*)d_in[0];
    const int*   eidx = (const int*)d_in[1];
    const float* ea   = (const float*)d_in[2];
    const float* Wq   = (const float*)d_in[3];
    const float* bq   = (const float*)d_in[4];
    const float* Wk   = (const float*)d_in[5];
    const float* bk   = (const float*)d_in[6];
    const float* Wv   = (const float*)d_in[7];
    const float* bv   = (const float*)d_in[8];
    const float* We   = (const float*)d_in[9];
    const float* be   = (const float*)d_in[10];
    const float* Ws   = (const float*)d_in[11];
    const float* bs   = (const float*)d_in[12];
    float*       out  = (float*)d_out;

    float *dq, *dk, *dv, *dskip, *de;
    cudaGetSymbolAddress((void**)&dq,    g_q);
    cudaGetSymbolAddress((void**)&dk,    g_k);
    cudaGetSymbolAddress((void**)&dv,    g_v);
    cudaGetSymbolAddress((void**)&dskip, g_skip);
    cudaGetSymbolAddress((void**)&de,    g_e);

    // node projections: M=50000, N=128, K=256
    {
        dim3 grid(1, (N_NODES + 127) / 128);
        sgemm_bias<128,128,8,8,8><<<grid, 256>>>(x, Wq, bq, dq,    N_NODES, OUT_SIZE, IN_SIZE);
        sgemm_bias<128,128,8,8,8><<<grid, 256>>>(x, Wk, bk, dk,    N_NODES, OUT_SIZE, IN_SIZE);
        sgemm_bias<128,128,8,8,8><<<grid, 256>>>(x, Wv, bv, dv,    N_NODES, OUT_SIZE, IN_SIZE);
        sgemm_bias<128,128,8,8,8><<<grid, 256>>>(x, Ws, bs, dskip, N_NODES, OUT_SIZE, IN_SIZE);
    }
    // edge projection: M=800000, N=128, K=64
    {
        dim3 grid(1, N_EDGES / 128);
        sgemm_bias<128,128,8,8,8><<<grid, 256>>>(ea, We, be, de, N_EDGES, OUT_SIZE, EDGE_DIM);
    }

    // CSR build
    zero_deg_kernel<<<(N_NODES + 255) / 256, 256>>>();
    count_kernel<<<(N_EDGES + 255) / 256, 256>>>(eidx);
    scan_kernel<<<1, 1024>>>();
    scatter_kernel<<<(N_EDGES + 255) / 256, 256>>>(eidx);

    // fused attention + aggregation + skip + ELU
    attn_kernel<<<(N_NODES + 7) / 8, 256>>>(eidx, out);
}

// round 5
// speedup vs baseline: 1.0662x; 1.0662x over previous
#include <cuda_runtime.h>
#include <cuda_bf16.h>
#include <math.h>
#include <stdint.h>

#define N_NODES 50000
#define N_EDGES 800000
#define IN_SIZE 256
#define OUT_SIZE 128
#define EDGE_DIM 64

// ---------------- scratch (static device globals; no runtime allocation) ----
__device__ float g_proj[(size_t)N_NODES * 512];          // rows: [q|k|v|skip] packed, stride 512
__device__ float g_qe[(size_t)N_NODES * EDGE_DIM];       // We @ q per node
__device__ float g_aggv[(size_t)N_NODES * OUT_SIZE];     // softmax-weighted v-sum (+flag*be)
__device__ float g_agge[(size_t)N_NODES * EDGE_DIM];     // softmax-weighted edge_attr-sum
__device__ float g_Wcat[256 * 512];                      // [K=256][N=512] = Wq|Wk|Wv|Ws
__device__ float g_bcat[512];
__device__ float g_WeT[128 * 64];                        // [K=128][N=64] = We^T
__device__ float g_zero128[128];
__device__ int   g_deg[N_NODES];
__device__ int   g_off[N_NODES + 1];
__device__ int   g_cur[N_NODES];
__device__ int   g_eorder[N_EDGES];

__device__ __forceinline__ int clamp_node(int v) {
    return (v < 0) ? 0 : ((v >= N_NODES) ? N_NODES - 1 : v);
}

// ---------------- SGEMM: C[M,N] = A[M,K](lda) @ B[K,N] + bias[N] (+adds, elu)
// BM x BN tile, BK=8, 256 threads, TM x TN per-thread tile (TM*TN = BM*BN/256).
// REQUIRES TN % 4 == 0 (float4 epilogue).
template <int BM, int BN, int BK, int TM, int TN>
__global__ __launch_bounds__(256) void sgemm_bias(
    const float* __restrict__ A, int lda,
    const float* __restrict__ B,
    const float* __restrict__ bias, float* __restrict__ C,
    const float* __restrict__ add1, int as1,
    const float* __restrict__ add2, int as2,
    int do_elu, int M, int N, int K)
{
    static_assert(TN % 4 == 0, "float4 epilogue requires TN % 4 == 0");
    static_assert(TM * TN * 256 == BM * BN, "thread tile mismatch");

    __shared__ float As[BK][BM];
    __shared__ float Bs[BK][BN];

    const int tid  = threadIdx.x;
    const int row0 = blockIdx.y * BM;
    const int col0 = blockIdx.x * BN;

    const int tRow = (tid / (BN / TN)) * TM;
    const int tCol = (tid % (BN / TN)) * TN;

    const int aRow = tid / (BK / 4);
    const int aCol = (tid % (BK / 4)) * 4;
    const int bRow = tid / (BN / 4);
    const int bCol = (tid % (BN / 4)) * 4;

    float acc[TM][TN];
#pragma unroll
    for (int i = 0; i < TM; i++)
#pragma unroll
        for (int j = 0; j < TN; j++) acc[i][j] = 0.0f;

    for (int k0 = 0; k0 < K; k0 += BK) {
        float4 av = make_float4(0.f, 0.f, 0.f, 0.f);
        if (row0 + aRow < M)
            av = *(const float4*)(A + (size_t)(row0 + aRow) * lda + k0 + aCol);
        As[aCol + 0][aRow] = av.x;
        As[aCol + 1][aRow] = av.y;
        As[aCol + 2][aRow] = av.z;
        As[aCol + 3][aRow] = av.w;

        if (bRow < BK) {
            float4 bv = *(const float4*)(B + (size_t)(k0 + bRow) * N + col0 + bCol);
            *(float4*)&Bs[bRow][bCol] = bv;
        }
        __syncthreads();

        float regM[TM], regN[TN];
#pragma unroll
        for (int kk = 0; kk < BK; kk++) {
#pragma unroll
            for (int i = 0; i < TM; i++) regM[i] = As[kk][tRow + i];
#pragma unroll
            for (int j = 0; j < TN; j++) regN[j] = Bs[kk][tCol + j];
#pragma unroll
            for (int i = 0; i < TM; i++)
#pragma unroll
                for (int j = 0; j < TN; j++)
                    acc[i][j] = fmaf(regM[i], regN[j], acc[i][j]);
        }
        __syncthreads();
    }

#pragma unroll
    for (int i = 0; i < TM; i++) {
        int r = row0 + tRow + i;
        if (r >= M) continue;
#pragma unroll
        for (int j = 0; j < TN; j += 4) {
            int c = col0 + tCol + j;
            float4 o;
            o.x = acc[i][j + 0] + bias[c + 0];
            o.y = acc[i][j + 1] + bias[c + 1];
            o.z = acc[i][j + 2] + bias[c + 2];
            o.w = acc[i][j + 3] + bias[c + 3];
            if (add1) {
                float4 a1 = *(const float4*)(add1 + (size_t)r * as1 + c);
                o.x += a1.x; o.y += a1.y; o.z += a1.z; o.w += a1.w;
            }
            if (add2) {
                float4 a2 = *(const float4*)(add2 + (size_t)r * as2 + c);
                o.x += a2.x; o.y += a2.y; o.z += a2.z; o.w += a2.w;
            }
            if (do_elu) {
                o.x = (o.x > 0.f) ? o.x : expm1f(o.x);
                o.y = (o.y > 0.f) ? o.y : expm1f(o.y);
                o.z = (o.z > 0.f) ? o.z : expm1f(o.z);
                o.w = (o.w > 0.f) ? o.w : expm1f(o.w);
            }
            *(float4*)(C + (size_t)r * N + c) = o;
        }
    }
}

// ---------------- weight prep -------------------------------------------------
__global__ void prep_weights(const float* __restrict__ Wq, const float* __restrict__ Wk,
                             const float* __restrict__ Wv, const float* __restrict__ Ws,
                             const float* __restrict__ bq, const float* __restrict__ bk,
                             const float* __restrict__ bv, const float* __restrict__ bs,
                             const float* __restrict__ We) {
    int idx = blockIdx.x * blockDim.x + threadIdx.x;
    if (idx < 256 * 512) {
        int k = idx / 512, col = idx % 512;
        int g = col / 128, n = col % 128;
        const float* W = (g == 0) ? Wq : (g == 1) ? Wk : (g == 2) ? Wv : Ws;
        g_Wcat[k * 512 + col] = W[k * 128 + n];
    }
    if (idx < 512) {
        const float* b = (idx < 128) ? bq : (idx < 256) ? bk : (idx < 384) ? bv : bs;
        g_bcat[idx] = b[idx % 128];
    }
    if (idx < 128 * 64) {
        int c = idx / 64, d = idx % 64;
        g_WeT[c * 64 + d] = We[d * 128 + c];
    }
    if (idx < 128) g_zero128[idx] = 0.f;
}

// ---------------- CSR build ---------------------------------------------
__global__ void zero_deg_kernel() {
    int i = blockIdx.x * blockDim.x + threadIdx.x;
    if (i < N_NODES) g_deg[i] = 0;
}
__global__ void count_kernel(const int* __restrict__ edge_index) {
    int i = blockIdx.x * blockDim.x + threadIdx.x;
    if (i < N_EDGES) atomicAdd(&g_deg[clamp_node(edge_index[N_EDGES + i])], 1);
}
__global__ void scan_kernel() {
    __shared__ int sums[1024];
    const int CH = (N_NODES + 1023) / 1024;
    int t = threadIdx.x;
    int base = t * CH;
    int sum = 0;
    for (int j = 0; j < CH; j++) {
        int idx = base + j;
        if (idx < N_NODES) sum += g_deg[idx];
    }
    sums[t] = sum;
    __syncthreads();
    for (int off = 1; off < 1024; off *= 2) {
        int v = (t >= off) ? sums[t - off] : 0;
        __syncthreads();
        sums[t] += v;
        __syncthreads();
    }
    int run = (t == 0) ? 0 : sums[t - 1];
    for (int j = 0; j < CH; j++) {
        int idx = base + j;
        if (idx < N_NODES) {
            g_off[idx] = run;
            g_cur[idx] = run;
            run += g_deg[idx];
        }
    }
    if (t == 1023) g_off[N_NODES] = run;
}
__global__ void scatter_kernel(const int* __restrict__ edge_index) {
    int i = blockIdx.x * blockDim.x + threadIdx.x;
    if (i < N_EDGES) {
        int dst = clamp_node(edge_index[N_EDGES + i]);
        int p = atomicAdd(&g_cur[dst], 1);
        if (p >= 0 && p < N_EDGES) g_eorder[p] = i;
    }
}

// ---------------- fused attention (64-dim edge_attr path) --------------------
// one warp per destination node; online softmax; no float atomics.
// score_e = (q[dst].k[src] + qe[dst].edge_attr_e) / sqrt(128)
// outputs: g_aggv = sum a_e * v[src] + flag*be ; g_agge = sum a_e * edge_attr_e
__global__ __launch_bounds__(256) void attn_kernel(
    const int* __restrict__ edge_index, const float* __restrict__ edge_attr,
    const float* __restrict__ be)
{
    const int warp = threadIdx.x / 32;
    const int lane = threadIdx.x % 32;
    const int node = blockIdx.x * 8 + warp;
    if (node >= N_NODES) return;

    const float* prow = g_proj + (size_t)node * 512;
    const float4 qv = *(const float4*)(prow + lane * 4);            // q plane
    const float2 qe = *(const float2*)(g_qe + (size_t)node * 64 + lane * 2);

    float4 accv = make_float4(0.f, 0.f, 0.f, 0.f);
    float2 acce = make_float2(0.f, 0.f);
    float m = -INFINITY;
    float s = 0.f;

    int beg = g_off[node];
    int end = g_off[node + 1];
    if (beg < 0) beg = 0;
    if (end > N_EDGES) end = N_EDGES;

    for (int p = beg; p < end; p++) {
        const int ei  = g_eorder[p];
        const int src = clamp_node(__ldg(&edge_index[ei]));

        const float* srow = g_proj + (size_t)src * 512;
        const float4 kv = *(const float4*)(srow + 128 + lane * 4);  // k plane
        const float4 vv = *(const float4*)(srow + 256 + lane * 4);  // v plane
        const float2 ea = *(const float2*)(edge_attr + (size_t)ei * 64 + lane * 2);

        float d = fmaf(qv.x, kv.x,
                  fmaf(qv.y, kv.y,
                  fmaf(qv.z, kv.z,
                  fmaf(qv.w, kv.w,
                  fmaf(qe.x, ea.x, qe.y * ea.y)))));
#pragma unroll
        for (int off = 16; off > 0; off >>= 1)
            d += __shfl_xor_sync(0xFFFFFFFFu, d, off);

        const float alpha = d * 0.08838834764831845f;   // 1/sqrt(128)
        const float nm = fmaxf(m, alpha);
        const float f  = __expf(m - nm);      // 0 on first edge (m = -inf)
        const float w  = __expf(alpha - nm);
        s = s * f + w;
        accv.x = fmaf(w, vv.x, accv.x * f);
        accv.y = fmaf(w, vv.y, accv.y * f);
        accv.z = fmaf(w, vv.z, accv.z * f);
        accv.w = fmaf(w, vv.w, accv.w * f);
        acce.x = fmaf(w, ea.x, acce.x * f);
        acce.y = fmaf(w, ea.y, acce.y * f);
        m = nm;
    }

    const float inv  = 1.0f / (s + 1e-16f);
    const float flag = (end > beg) ? 1.0f : 0.0f;
    const float4 bev = *(const float4*)(be + lane * 4);

    float4 ov;
    ov.x = fmaf(accv.x, inv, flag * bev.x);
    ov.y = fmaf(accv.y, inv, flag * bev.y);
    ov.z = fmaf(accv.z, inv, flag * bev.z);
    ov.w = fmaf(accv.w, inv, flag * bev.w);
    *(float4*)(g_aggv + (size_t)node * 128 + lane * 4) = ov;

    float2 oe;
    oe.x = acce.x * inv;
    oe.y = acce.y * inv;
    *(float2*)(g_agge + (size_t)node * 64 + lane * 2) = oe;
}

// ---------------- launch -----------------------------------------------------
extern "C" void kernel_launch(void* const* d_in, const int* in_sizes, int n_in,
                              void* d_out, int out_size)
{
    const float* x    = (const float*)d_in[0];
    const int*   eidx = (const int*)d_in[1];
    const float* ea   = (const float*)d_in[2];
    const float* Wq   = (const float*)d_in[3];
    const float* bq   = (const float*)d_in[4];
    const float* Wk   = (const float*)d_in[5];
    const float* bk   = (const float*)d_in[6];
    const float* Wv   = (const float*)d_in[7];
    const float* bv   = (const float*)d_in[8];
    const float* We   = (const float*)d_in[9];
    const float* be   = (const float*)d_in[10];
    const float* Ws   = (const float*)d_in[11];
    const float* bs   = (const float*)d_in[12];
    float*       out  = (float*)d_out;

    float *dproj, *dqe, *daggv, *dagge, *dWcat, *dbcat, *dWeT, *dzero;
    cudaGetSymbolAddress((void**)&dproj, g_proj);
    cudaGetSymbolAddress((void**)&dqe,   g_qe);
    cudaGetSymbolAddress((void**)&daggv, g_aggv);
    cudaGetSymbolAddress((void**)&dagge, g_agge);
    cudaGetSymbolAddress((void**)&dWcat, g_Wcat);
    cudaGetSymbolAddress((void**)&dbcat, g_bcat);
    cudaGetSymbolAddress((void**)&dWeT,  g_WeT);
    cudaGetSymbolAddress((void**)&dzero, g_zero128);

    // weight prep (Wcat, bcat, WeT, zeros)
    prep_weights<<<(256 * 512 + 255) / 256, 256>>>(Wq, Wk, Wv, Ws, bq, bk, bv, bs, We);

    // CSR build (independent of GEMMs)
    zero_deg_kernel<<<(N_NODES + 255) / 256, 256>>>();
    count_kernel<<<(N_EDGES + 255) / 256, 256>>>(eidx);
    scan_kernel<<<1, 1024>>>();
    scatter_kernel<<<(N_EDGES + 255) / 256, 256>>>(eidx);

    // fused node projections: proj[M,512] = x[M,256] @ Wcat[256,512] + bcat
    {
        dim3 grid(4, (N_NODES + 127) / 128);
        sgemm_bias<128, 128, 8, 8, 8><<<grid, 256>>>(
            x, IN_SIZE, dWcat, dbcat, dproj,
            nullptr, 0, nullptr, 0, 0, N_NODES, 512, 256);
    }
    // qe[M,64] = q[M,128] @ WeT[128,64]   (q = proj plane 0, lda=512)
    {
        dim3 grid(1, (N_NODES + 127) / 128);
        sgemm_bias<128, 64, 8, 8, 4><<<grid, 256>>>(
            dproj, 512, dWeT, dzero, dqe,
            nullptr, 0, nullptr, 0, 0, N_NODES, 64, 128);
    }

    // fused attention: aggv, agge
    attn_kernel<<<(N_NODES + 7) / 8, 256>>>(eidx, ea, be);

    // out = agge[M,64] @ We[64,128] + aggv + skip, then ELU (writes d_out)
    {
        dim3 grid(1, (N_NODES + 127) / 128);
        sgemm_bias<128, 128, 8, 8, 8><<<grid, 256>>>(
            dagge, EDGE_DIM, We, dzero, out,
            daggv, 128, dproj + 384, 512, 1, N_NODES, 128, 64);
    }
}

// round 6
// speedup vs baseline: 1.7580x; 1.6489x over previous
#include <cuda_runtime.h>
#include <cuda_bf16.h>
#include <math.h>
#include <stdint.h>

#define N_NODES 50000
#define N_EDGES 800000
#define IN_SIZE 256
#define OUT_SIZE 128
#define EDGE_DIM 64
#define SCAN_BLOCKS ((N_NODES + 255) / 256)   // 196

// ---------------- scratch (static device globals; no runtime allocation) ----
__device__ float g_proj[(size_t)N_NODES * 512];          // rows: [q|k|v|skip] packed, stride 512
__device__ float g_qe[(size_t)N_NODES * EDGE_DIM];       // We @ q per node
__device__ float g_aggv[(size_t)N_NODES * OUT_SIZE];     // softmax-weighted v-sum (+flag*be)
__device__ float g_agge[(size_t)N_NODES * EDGE_DIM];     // softmax-weighted edge_attr-sum
__device__ float g_Wcat[256 * 512];                      // [K=256][N=512] = Wq|Wk|Wv|Ws
__device__ float g_bcat[512];
__device__ float g_WeT[128 * 64];                        // [K=128][N=64] = We^T
__device__ float g_zero128[128];
__device__ int   g_deg[N_NODES];
__device__ int   g_off[N_NODES + 1];
__device__ int   g_cur[N_NODES];
__device__ int   g_eorder[N_EDGES];
__device__ int   g_part[SCAN_BLOCKS];

__device__ __forceinline__ int clamp_node(int v) {
    return (v < 0) ? 0 : ((v >= N_NODES) ? N_NODES - 1 : v);
}

// ---------------- double-buffered SGEMM --------------------------------------
// C[M,N] = A[M,K](lda) @ B[K,N] + bias[N] (+adds, elu)
// BM x BN tile, BK=8, 256 threads, TM x TN per-thread tile. TN % 4 == 0.
template <int BM, int BN, int BK, int TM, int TN>
__global__ __launch_bounds__(256) void sgemm_bias(
    const float* __restrict__ A, int lda,
    const float* __restrict__ B,
    const float* __restrict__ bias, float* __restrict__ C,
    const float* __restrict__ add1, int as1,
    const float* __restrict__ add2, int as2,
    int do_elu, int M, int N, int K)
{
    static_assert(TN % 4 == 0, "float4 epilogue requires TN % 4 == 0");
    static_assert(TM * TN * 256 == BM * BN, "thread tile mismatch");

    __shared__ float As[2][BK][BM];
    __shared__ float Bs[2][BK][BN];

    const int tid  = threadIdx.x;
    const int row0 = blockIdx.y * BM;
    const int col0 = blockIdx.x * BN;

    const int tRow = (tid / (BN / TN)) * TM;
    const int tCol = (tid % (BN / TN)) * TN;

    const int aRow = tid / (BK / 4);
    const int aCol = (tid % (BK / 4)) * 4;
    const int bRow = tid / (BN / 4);
    const int bCol = (tid % (BN / 4)) * 4;

    float acc[TM][TN];
#pragma unroll
    for (int i = 0; i < TM; i++)
#pragma unroll
        for (int j = 0; j < TN; j++) acc[i][j] = 0.0f;

    // preload k0 = 0 into buffer 0
    {
        float4 av = make_float4(0.f, 0.f, 0.f, 0.f);
        if (row0 + aRow < M)
            av = *(const float4*)(A + (size_t)(row0 + aRow) * lda + aCol);
        As[0][aCol + 0][aRow] = av.x;
        As[0][aCol + 1][aRow] = av.y;
        As[0][aCol + 2][aRow] = av.z;
        As[0][aCol + 3][aRow] = av.w;
        if (bRow < BK)
            *(float4*)&Bs[0][bRow][bCol] = *(const float4*)(B + (size_t)bRow * N + col0 + bCol);
    }
    __syncthreads();

    int buf = 0;
    for (int k0 = BK; k0 < K + BK; k0 += BK) {
        const bool has = (k0 < K);
        float4 aNext = make_float4(0.f, 0.f, 0.f, 0.f);
        float4 bNext;
        if (has) {
            if (row0 + aRow < M)
                aNext = *(const float4*)(A + (size_t)(row0 + aRow) * lda + k0 + aCol);
            if (bRow < BK)
                bNext = *(const float4*)(B + (size_t)(k0 + bRow) * N + col0 + bCol);
        }

        float regM[TM], regN[TN];
#pragma unroll
        for (int kk = 0; kk < BK; kk++) {
#pragma unroll
            for (int i = 0; i < TM; i++) regM[i] = As[buf][kk][tRow + i];
#pragma unroll
            for (int j = 0; j < TN; j++) regN[j] = Bs[buf][kk][tCol + j];
#pragma unroll
            for (int i = 0; i < TM; i++)
#pragma unroll
                for (int j = 0; j < TN; j++)
                    acc[i][j] = fmaf(regM[i], regN[j], acc[i][j]);
        }

        if (has) {
            const int nb = buf ^ 1;
            As[nb][aCol + 0][aRow] = aNext.x;
            As[nb][aCol + 1][aRow] = aNext.y;
            As[nb][aCol + 2][aRow] = aNext.z;
            As[nb][aCol + 3][aRow] = aNext.w;
            if (bRow < BK)
                *(float4*)&Bs[nb][bRow][bCol] = bNext;
            __syncthreads();
            buf = nb;
        }
    }

#pragma unroll
    for (int i = 0; i < TM; i++) {
        int r = row0 + tRow + i;
        if (r >= M) continue;
#pragma unroll
        for (int j = 0; j < TN; j += 4) {
            int c = col0 + tCol + j;
            float4 o;
            o.x = acc[i][j + 0] + bias[c + 0];
            o.y = acc[i][j + 1] + bias[c + 1];
            o.z = acc[i][j + 2] + bias[c + 2];
            o.w = acc[i][j + 3] + bias[c + 3];
            if (add1) {
                float4 a1 = *(const float4*)(add1 + (size_t)r * as1 + c);
                o.x += a1.x; o.y += a1.y; o.z += a1.z; o.w += a1.w;
            }
            if (add2) {
                float4 a2 = *(const float4*)(add2 + (size_t)r * as2 + c);
                o.x += a2.x; o.y += a2.y; o.z += a2.z; o.w += a2.w;
            }
            if (do_elu) {
                o.x = (o.x > 0.f) ? o.x : expm1f(o.x);
                o.y = (o.y > 0.f) ? o.y : expm1f(o.y);
                o.z = (o.z > 0.f) ? o.z : expm1f(o.z);
                o.w = (o.w > 0.f) ? o.w : expm1f(o.w);
            }
            *(float4*)(C + (size_t)r * N + c) = o;
        }
    }
}

// ---------------- weight prep -------------------------------------------------
__global__ void prep_weights(const float* __restrict__ Wq, const float* __restrict__ Wk,
                             const float* __restrict__ Wv, const float* __restrict__ Ws,
                             const float* __restrict__ bq, const float* __restrict__ bk,
                             const float* __restrict__ bv, const float* __restrict__ bs,
                             const float* __restrict__ We) {
    int idx = blockIdx.x * blockDim.x + threadIdx.x;
    if (idx < 256 * 512) {
        int k = idx / 512, col = idx % 512;
        int g = col / 128, n = col % 128;
        const float* W = (g == 0) ? Wq : (g == 1) ? Wk : (g == 2) ? Wv : Ws;
        g_Wcat[k * 512 + col] = W[k * 128 + n];
    }
    if (idx < 512) {
        const float* b = (idx < 128) ? bq : (idx < 256) ? bk : (idx < 384) ? bv : bs;
        g_bcat[idx] = b[idx % 128];
    }
    if (idx < 128 * 64) {
        int c = idx / 64, d = idx % 64;
        g_WeT[c * 64 + d] = We[d * 128 + c];
    }
    if (idx < 128) g_zero128[idx] = 0.f;
}

// ---------------- CSR build (parallel scan) -----------------------------------
__global__ void zero_deg_kernel() {
    int i = blockIdx.x * blockDim.x + threadIdx.x;
    if (i < N_NODES) g_deg[i] = 0;
}
__global__ void count_kernel(const int* __restrict__ edge_index) {
    int i = blockIdx.x * blockDim.x + threadIdx.x;
    if (i < N_EDGES) atomicAdd(&g_deg[clamp_node(edge_index[N_EDGES + i])], 1);
}
// per-block partial sums of degrees
__global__ __launch_bounds__(256) void reduce_deg_kernel() {
    __shared__ int sm[256];
    int t = threadIdx.x;
    int i = blockIdx.x * 256 + t;
    sm[t] = (i < N_NODES) ? g_deg[i] : 0;
    __syncthreads();
#pragma unroll
    for (int s = 128; s > 0; s >>= 1) {
        if (t < s) sm[t] += sm[t + s];
        __syncthreads();
    }
    if (t == 0) g_part[blockIdx.x] = sm[0];
}
// single-block exclusive scan of the 196 partials
__global__ __launch_bounds__(256) void scan_parts_kernel() {
    __shared__ int sp[256];
    int t = threadIdx.x;
    int v = (t < SCAN_BLOCKS) ? g_part[t] : 0;
    sp[t] = v;
    __syncthreads();
#pragma unroll
    for (int off = 1; off < 256; off <<= 1) {
        int u = (t >= off) ? sp[t - off] : 0;
        __syncthreads();
        sp[t] += u;
        __syncthreads();
    }
    if (t < SCAN_BLOCKS) g_part[t] = sp[t] - v;   // exclusive
}
// per-block exclusive scan + global offset; writes g_off / g_cur
__global__ __launch_bounds__(256) void write_off_kernel() {
    __shared__ int sc[256];
    int t = threadIdx.x;
    int i = blockIdx.x * 256 + t;
    int d = (i < N_NODES) ? g_deg[i] : 0;
    sc[t] = d;
    __syncthreads();
#pragma unroll
    for (int off = 1; off < 256; off <<= 1) {
        int u = (t >= off) ? sc[t - off] : 0;
        __syncthreads();
        sc[t] += u;
        __syncthreads();
    }
    int excl = sc[t] - d + g_part[blockIdx.x];
    if (i < N_NODES) {
        g_off[i] = excl;
        g_cur[i] = excl;
        if (i == N_NODES - 1) g_off[N_NODES] = excl + d;
    }
}
__global__ void scatter_kernel(const int* __restrict__ edge_index) {
    int i = blockIdx.x * blockDim.x + threadIdx.x;
    if (i < N_EDGES) {
        int dst = clamp_node(edge_index[N_EDGES + i]);
        int p = atomicAdd(&g_cur[dst], 1);
        if (p >= 0 && p < N_EDGES) g_eorder[p] = i;
    }
}

// ---------------- fused attention (64-dim edge_attr path) --------------------
// one warp per destination node; online softmax; no float atomics.
// score_e = (q[dst].k[src] + qe[dst].edge_attr_e) / sqrt(128)
__global__ __launch_bounds__(256) void attn_kernel(
    const int* __restrict__ edge_index, const float* __restrict__ edge_attr,
    const float* __restrict__ be)
{
    const int warp = threadIdx.x / 32;
    const int lane = threadIdx.x % 32;
    const int node = blockIdx.x * 8 + warp;
    if (node >= N_NODES) return;

    const float* prow = g_proj + (size_t)node * 512;
    const float4 qv = *(const float4*)(prow + lane * 4);            // q plane
    const float2 qe = *(const float2*)(g_qe + (size_t)node * 64 + lane * 2);

    float4 accv = make_float4(0.f, 0.f, 0.f, 0.f);
    float2 acce = make_float2(0.f, 0.f);
    float m = -INFINITY;
    float s = 0.f;

    int beg = g_off[node];
    int end = g_off[node + 1];
    if (beg < 0) beg = 0;
    if (end > N_EDGES) end = N_EDGES;

    for (int p = beg; p < end; p++) {
        const int ei  = g_eorder[p];
        const int src = clamp_node(__ldg(&edge_index[ei]));

        const float* srow = g_proj + (size_t)src * 512;
        const float4 kv = *(const float4*)(srow + 128 + lane * 4);  // k plane
        const float4 vv = *(const float4*)(srow + 256 + lane * 4);  // v plane
        const float2 ea = *(const float2*)(edge_attr + (size_t)ei * 64 + lane * 2);

        float d = fmaf(qv.x, kv.x,
                  fmaf(qv.y, kv.y,
                  fmaf(qv.z, kv.z,
                  fmaf(qv.w, kv.w,
                  fmaf(qe.x, ea.x, qe.y * ea.y)))));
#pragma unroll
        for (int off = 16; off > 0; off >>= 1)
            d += __shfl_xor_sync(0xFFFFFFFFu, d, off);

        const float alpha = d * 0.08838834764831845f;   // 1/sqrt(128)
        const float nm = fmaxf(m, alpha);
        const float f  = __expf(m - nm);      // 0 on first edge (m = -inf)
        const float w  = __expf(alpha - nm);
        s = s * f + w;
        accv.x = fmaf(w, vv.x, accv.x * f);
        accv.y = fmaf(w, vv.y, accv.y * f);
        accv.z = fmaf(w, vv.z, accv.z * f);
        accv.w = fmaf(w, vv.w, accv.w * f);
        acce.x = fmaf(w, ea.x, acce.x * f);
        acce.y = fmaf(w, ea.y, acce.y * f);
        m = nm;
    }

    const float inv  = 1.0f / (s + 1e-16f);
    const float flag = (end > beg) ? 1.0f : 0.0f;
    const float4 bev = *(const float4*)(be + lane * 4);

    float4 ov;
    ov.x = fmaf(accv.x, inv, flag * bev.x);
    ov.y = fmaf(accv.y, inv, flag * bev.y);
    ov.z = fmaf(accv.z, inv, flag * bev.z);
    ov.w = fmaf(accv.w, inv, flag * bev.w);
    *(float4*)(g_aggv + (size_t)node * 128 + lane * 4) = ov;

    float2 oe;
    oe.x = acce.x * inv;
    oe.y = acce.y * inv;
    *(float2*)(g_agge + (size_t)node * 64 + lane * 2) = oe;
}

// ---------------- launch -----------------------------------------------------
extern "C" void kernel_launch(void* const* d_in, const int* in_sizes, int n_in,
                              void* d_out, int out_size)
{
    const float* x    = (const float*)d_in[0];
    const int*   eidx = (const int*)d_in[1];
    const float* ea   = (const float*)d_in[2];
    const float* Wq   = (const float*)d_in[3];
    const float* bq   = (const float*)d_in[4];
    const float* Wk   = (const float*)d_in[5];
    const float* bk   = (const float*)d_in[6];
    const float* Wv   = (const float*)d_in[7];
    const float* bv   = (const float*)d_in[8];
    const float* We   = (const float*)d_in[9];
    const float* be   = (const float*)d_in[10];
    const float* Ws   = (const float*)d_in[11];
    const float* bs   = (const float*)d_in[12];
    float*       out  = (float*)d_out;

    float *dproj, *dqe, *daggv, *dagge, *dWcat, *dbcat, *dWeT, *dzero;
    cudaGetSymbolAddress((void**)&dproj, g_proj);
    cudaGetSymbolAddress((void**)&dqe,   g_qe);
    cudaGetSymbolAddress((void**)&daggv, g_aggv);
    cudaGetSymbolAddress((void**)&dagge, g_agge);
    cudaGetSymbolAddress((void**)&dWcat, g_Wcat);
    cudaGetSymbolAddress((void**)&dbcat, g_bcat);
    cudaGetSymbolAddress((void**)&dWeT,  g_WeT);
    cudaGetSymbolAddress((void**)&dzero, g_zero128);

    // weight prep (Wcat, bcat, WeT, zeros)
    prep_weights<<<(256 * 512 + 255) / 256, 256>>>(Wq, Wk, Wv, Ws, bq, bk, bv, bs, We);

    // CSR build
    zero_deg_kernel<<<(N_NODES + 255) / 256, 256>>>();
    count_kernel<<<(N_EDGES + 255) / 256, 256>>>(eidx);
    reduce_deg_kernel<<<SCAN_BLOCKS, 256>>>();
    scan_parts_kernel<<<1, 256>>>();
    write_off_kernel<<<SCAN_BLOCKS, 256>>>();
    scatter_kernel<<<(N_EDGES + 255) / 256, 256>>>(eidx);

    // fused node projections: proj[M,512] = x[M,256] @ Wcat[256,512] + bcat
    {
        dim3 grid(4, (N_NODES + 127) / 128);
        sgemm_bias<128, 128, 8, 8, 8><<<grid, 256>>>(
            x, IN_SIZE, dWcat, dbcat, dproj,
            nullptr, 0, nullptr, 0, 0, N_NODES, 512, 256);
    }
    // qe[M,64] = q[M,128] @ WeT[128,64]   (q = proj plane 0, lda=512)
    {
        dim3 grid(1, (N_NODES + 127) / 128);
        sgemm_bias<128, 64, 8, 8, 4><<<grid, 256>>>(
            dproj, 512, dWeT, dzero, dqe,
            nullptr, 0, nullptr, 0, 0, N_NODES, 64, 128);
    }

    // fused attention: aggv, agge
    attn_kernel<<<(N_NODES + 7) / 8, 256>>>(eidx, ea, be);

    // out = agge[M,64] @ We[64,128] + aggv + skip, then ELU (writes d_out)
    {
        dim3 grid(1, (N_NODES + 127) / 128);
        sgemm_bias<128, 128, 8, 8, 8><<<grid, 256>>>(
            dagge, EDGE_DIM, We, dzero, out,
            daggv, 128, dproj + 384, 512, 1, N_NODES, 128, 64);
    }
}

// round 7
// speedup vs baseline: 2.6237x; 1.4924x over previous
#include <cuda_runtime.h>
#include <cuda_bf16.h>
#include <math.h>
#include <stdint.h>

#define N_NODES 50000
#define N_EDGES 800000
#define IN_SIZE 256
#define OUT_SIZE 128
#define EDGE_DIM 64
#define SCAN_BLOCKS ((N_NODES + 255) / 256)   // 196

// ---------------- scratch (static device globals; no runtime allocation) ----
__device__ float g_proj[(size_t)N_NODES * 512];          // rows: [q|k|v|skip], stride 512
__device__ float g_qe[(size_t)N_NODES * EDGE_DIM];
__device__ float g_aggv[(size_t)N_NODES * OUT_SIZE];
__device__ float g_agge[(size_t)N_NODES * EDGE_DIM];
__device__ __nv_bfloat16 g_xhi[(size_t)N_NODES * IN_SIZE];
__device__ __nv_bfloat16 g_xlo[(size_t)N_NODES * IN_SIZE];
__device__ __nv_bfloat16 g_WTh[512 * 256];               // [n=512][k=256] = Wcat^T hi
__device__ __nv_bfloat16 g_WTl[512 * 256];
__device__ float g_bcat[512];
__device__ float g_WeT[128 * 64];                        // [K=128][N=64] = We^T
__device__ float g_zero128[128];
__device__ int   g_deg[N_NODES];
__device__ int   g_off[N_NODES + 1];
__device__ int   g_cur[N_NODES];
__device__ int   g_eorder[N_EDGES];
__device__ int   g_part[SCAN_BLOCKS];

__device__ __forceinline__ int clamp_node(int v) {
    return (v < 0) ? 0 : ((v >= N_NODES) ? N_NODES - 1 : v);
}
__device__ __forceinline__ uint32_t smem_u32(const void* p) {
    uint32_t a;
    asm("{ .reg .u64 t; cvta.to.shared.u64 t, %1; cvt.u32.u64 %0, t; }" : "=r"(a) : "l"(p));
    return a;
}

#define CPASYNC16(saddr, gptr) \
    asm volatile("cp.async.cg.shared.global [%0], [%1], 16;" :: "r"(saddr), "l"(gptr))
#define CP_COMMIT() asm volatile("cp.async.commit_group;" ::: "memory")
#define LDM4(d, addr) \
    asm volatile("ldmatrix.sync.aligned.m8n8.x4.shared.b16 {%0,%1,%2,%3}, [%4];" \
        : "=r"((d)[0]), "=r"((d)[1]), "=r"((d)[2]), "=r"((d)[3]) : "r"(addr))
#define MMA16816(c, a, b0v, b1v) \
    asm volatile("mma.sync.aligned.m16n8k16.row.col.f32.bf16.bf16.f32 " \
        "{%0,%1,%2,%3}, {%4,%5,%6,%7}, {%8,%9}, {%0,%1,%2,%3};" \
        : "+f"((c)[0]), "+f"((c)[1]), "+f"((c)[2]), "+f"((c)[3]) \
        : "r"((a)[0]), "r"((a)[1]), "r"((a)[2]), "r"((a)[3]), "r"(b0v), "r"(b1v))

// ---------------- bf16x3 tensor-core GEMM for node projections ---------------
// C[M=50000, 512] = x[M,256] @ Wcat[256,512] + bcat  (C = g_proj, stride 512)
// A = xhi+xlo (bf16), B = WTh+WTl ([n][k] bf16). acc += Ah*Bh + Ah*Bl + Al*Bh.
#define NSTAGE 8            // 256 / 32
#define SROWB  80           // bytes per row slot (32 bf16 + 8 pad)
#define OFF_AH 0
#define OFF_AL 10240
#define OFF_BH 20480
#define OFF_BL 30720
#define BUFSZ  40960
#define MMA_SMEM (2 * BUFSZ)   // 81920

__global__ __launch_bounds__(256, 2) void gemm_mma(
    const __nv_bfloat16* __restrict__ Ahg, const __nv_bfloat16* __restrict__ Alg,
    const __nv_bfloat16* __restrict__ Bhg, const __nv_bfloat16* __restrict__ Blg,
    const float* __restrict__ bias, float* __restrict__ C)
{
    extern __shared__ char sm[];
    const uint32_t sb = smem_u32(sm);
    const int tid  = threadIdx.x;
    const int lane = tid & 31, wid = tid >> 5;
    const int wm = wid >> 1, wn = wid & 1;        // 4 x 2 warp grid
    const int row0 = blockIdx.y * 128;
    const int col0 = blockIdx.x * 128;

    float acc[2][8][4];
#pragma unroll
    for (int m = 0; m < 2; m++)
#pragma unroll
        for (int n = 0; n < 8; n++)
#pragma unroll
            for (int i = 0; i < 4; i++) acc[m][n][i] = 0.f;

    // ldmatrix per-lane address components
    const int r8  = lane & 7, grp = lane >> 3;
    const int aRow = wm * 32 + ((grp & 1) << 3) + r8;   // + mt*16
    const int aKel = (grp >> 1) << 3;                   // + ks
    const int bRow = wn * 64 + ((grp >> 1) << 3) + r8;  // + p*16
    const int bKel = (grp & 1) << 3;                    // + ks

    // stage loader: 512 16B-chunks per array, 2 per thread per array
#define LOAD_STAGE(s) do {                                                      \
        const int k0 = (s) * 32;                                                \
        const uint32_t bb = sb + ((s) & 1) * BUFSZ;                             \
        _Pragma("unroll")                                                       \
        for (int c = 0; c < 2; c++) {                                           \
            int idx = tid * 2 + c;                                              \
            int row = idx >> 2, sub = idx & 3;                                  \
            int gr = row0 + row; if (gr >= N_NODES) gr = N_NODES - 1;           \
            size_t gaoff = (size_t)gr * IN_SIZE + k0 + sub * 8;                 \
            uint32_t soff = row * SROWB + sub * 16;                             \
            CPASYNC16(bb + OFF_AH + soff, Ahg + gaoff);                         \
            CPASYNC16(bb + OFF_AL + soff, Alg + gaoff);                         \
            size_t gboff = (size_t)(col0 + row) * IN_SIZE + k0 + sub * 8;       \
            CPASYNC16(bb + OFF_BH + soff, Bhg + gboff);                         \
            CPASYNC16(bb + OFF_BL + soff, Blg + gboff);                         \
        }                                                                       \
        CP_COMMIT();                                                            \
    } while (0)

    LOAD_STAGE(0);

    for (int s = 0; s < NSTAGE; s++) {
        if (s + 1 < NSTAGE) {
            LOAD_STAGE(s + 1);
            asm volatile("cp.async.wait_group 1;" ::: "memory");
        } else {
            asm volatile("cp.async.wait_group 0;" ::: "memory");
        }
        __syncthreads();

        const uint32_t bb = sb + (s & 1) * BUFSZ;
#pragma unroll
        for (int ks = 0; ks < 32; ks += 16) {
            uint32_t ah[2][4], al[2][4];
#pragma unroll
            for (int mt = 0; mt < 2; mt++) {
                uint32_t ad = bb + OFF_AH + (aRow + mt * 16) * SROWB + (aKel + ks) * 2;
                LDM4(ah[mt], ad);
                LDM4(al[mt], ad + (OFF_AL - OFF_AH));
            }
#pragma unroll
            for (int p = 0; p < 4; p++) {
                uint32_t bh[4], bl[4];
                uint32_t bd = bb + OFF_BH + (bRow + p * 16) * SROWB + (bKel + ks) * 2;
                LDM4(bh, bd);
                LDM4(bl, bd + (OFF_BL - OFF_BH));
#pragma unroll
                for (int mt = 0; mt < 2; mt++) {
#pragma unroll
                    for (int t = 0; t < 2; t++) {
                        float* cc = acc[mt][p * 2 + t];
                        MMA16816(cc, ah[mt], bh[2 * t], bh[2 * t + 1]);
                        MMA16816(cc, ah[mt], bl[2 * t], bl[2 * t + 1]);
                        MMA16816(cc, al[mt], bh[2 * t], bh[2 * t + 1]);
                    }
                }
            }
        }
        __syncthreads();
    }

    // epilogue: direct float2 stores + bias
#pragma unroll
    for (int mt = 0; mt < 2; mt++) {
        int r = row0 + wm * 32 + mt * 16 + (lane >> 2);
#pragma unroll
        for (int p = 0; p < 8; p++) {
            int col = col0 + wn * 64 + p * 8 + (lane & 3) * 2;
            float b0 = __ldg(bias + col), b1 = __ldg(bias + col + 1);
            if (r < N_NODES) {
                float2 o = make_float2(acc[mt][p][0] + b0, acc[mt][p][1] + b1);
                *(float2*)(C + (size_t)r * 512 + col) = o;
            }
            if (r + 8 < N_NODES) {
                float2 o = make_float2(acc[mt][p][2] + b0, acc[mt][p][3] + b1);
                *(float2*)(C + (size_t)(r + 8) * 512 + col) = o;
            }
        }
    }
#undef LOAD_STAGE
}

// ---------------- fp32 double-buffered SGEMM (small GEMMs) --------------------
template <int BM, int BN, int BK, int TM, int TN>
__global__ __launch_bounds__(256) void sgemm_bias(
    const float* __restrict__ A, int lda,
    const float* __restrict__ B,
    const float* __restrict__ bias, float* __restrict__ C,
    const float* __restrict__ add1, int as1,
    const float* __restrict__ add2, int as2,
    int do_elu, int M, int N, int K)
{
    static_assert(TN % 4 == 0, "float4 epilogue requires TN % 4 == 0");
    static_assert(TM * TN * 256 == BM * BN, "thread tile mismatch");

    __shared__ float As[2][BK][BM];
    __shared__ float Bs[2][BK][BN];

    const int tid  = threadIdx.x;
    const int row0 = blockIdx.y * BM;
    const int col0 = blockIdx.x * BN;

    const int tRow = (tid / (BN / TN)) * TM;
    const int tCol = (tid % (BN / TN)) * TN;

    const int aRow = tid / (BK / 4);
    const int aCol = (tid % (BK / 4)) * 4;
    const int bRow = tid / (BN / 4);
    const int bCol = (tid % (BN / 4)) * 4;

    float acc[TM][TN];
#pragma unroll
    for (int i = 0; i < TM; i++)
#pragma unroll
        for (int j = 0; j < TN; j++) acc[i][j] = 0.0f;

    {
        float4 av = make_float4(0.f, 0.f, 0.f, 0.f);
        if (row0 + aRow < M)
            av = *(const float4*)(A + (size_t)(row0 + aRow) * lda + aCol);
        As[0][aCol + 0][aRow] = av.x;
        As[0][aCol + 1][aRow] = av.y;
        As[0][aCol + 2][aRow] = av.z;
        As[0][aCol + 3][aRow] = av.w;
        if (bRow < BK)
            *(float4*)&Bs[0][bRow][bCol] = *(const float4*)(B + (size_t)bRow * N + col0 + bCol);
    }
    __syncthreads();

    int buf = 0;
    for (int k0 = BK; k0 < K + BK; k0 += BK) {
        const bool has = (k0 < K);
        float4 aNext = make_float4(0.f, 0.f, 0.f, 0.f);
        float4 bNext;
        if (has) {
            if (row0 + aRow < M)
                aNext = *(const float4*)(A + (size_t)(row0 + aRow) * lda + k0 + aCol);
            if (bRow < BK)
                bNext = *(const float4*)(B + (size_t)(k0 + bRow) * N + col0 + bCol);
        }

        float regM[TM], regN[TN];
#pragma unroll
        for (int kk = 0; kk < BK; kk++) {
#pragma unroll
            for (int i = 0; i < TM; i++) regM[i] = As[buf][kk][tRow + i];
#pragma unroll
            for (int j = 0; j < TN; j++) regN[j] = Bs[buf][kk][tCol + j];
#pragma unroll
            for (int i = 0; i < TM; i++)
#pragma unroll
                for (int j = 0; j < TN; j++)
                    acc[i][j] = fmaf(regM[i], regN[j], acc[i][j]);
        }

        if (has) {
            const int nb = buf ^ 1;
            As[nb][aCol + 0][aRow] = aNext.x;
            As[nb][aCol + 1][aRow] = aNext.y;
            As[nb][aCol + 2][aRow] = aNext.z;
            As[nb][aCol + 3][aRow] = aNext.w;
            if (bRow < BK)
                *(float4*)&Bs[nb][bRow][bCol] = bNext;
            __syncthreads();
            buf = nb;
        }
    }

#pragma unroll
    for (int i = 0; i < TM; i++) {
        int r = row0 + tRow + i;
        if (r >= M) continue;
#pragma unroll
        for (int j = 0; j < TN; j += 4) {
            int c = col0 + tCol + j;
            float4 o;
            o.x = acc[i][j + 0] + bias[c + 0];
            o.y = acc[i][j + 1] + bias[c + 1];
            o.z = acc[i][j + 2] + bias[c + 2];
            o.w = acc[i][j + 3] + bias[c + 3];
            if (add1) {
                float4 a1 = *(const float4*)(add1 + (size_t)r * as1 + c);
                o.x += a1.x; o.y += a1.y; o.z += a1.z; o.w += a1.w;
            }
            if (add2) {
                float4 a2 = *(const float4*)(add2 + (size_t)r * as2 + c);
                o.x += a2.x; o.y += a2.y; o.z += a2.z; o.w += a2.w;
            }
            if (do_elu) {
                o.x = (o.x > 0.f) ? o.x : expm1f(o.x);
                o.y = (o.y > 0.f) ? o.y : expm1f(o.y);
                o.z = (o.z > 0.f) ? o.z : expm1f(o.z);
                o.w = (o.w > 0.f) ? o.w : expm1f(o.w);
            }
            *(float4*)(C + (size_t)r * N + c) = o;
        }
    }
}

// ---------------- prep kernels ------------------------------------------------
__global__ void split_x_kernel(const float* __restrict__ x) {
    int i = blockIdx.x * blockDim.x + threadIdx.x;
    if (i < N_NODES * IN_SIZE / 4) {
        float4 v = ((const float4*)x)[i];
        __nv_bfloat16 hx = __float2bfloat16(v.x), hy = __float2bfloat16(v.y);
        __nv_bfloat16 hz = __float2bfloat16(v.z), hw = __float2bfloat16(v.w);
        __nv_bfloat16 lx = __float2bfloat16(v.x - __bfloat162float(hx));
        __nv_bfloat16 ly = __float2bfloat16(v.y - __bfloat162float(hy));
        __nv_bfloat16 lz = __float2bfloat16(v.z - __bfloat162float(hz));
        __nv_bfloat16 lw = __float2bfloat16(v.w - __bfloat162float(hw));
        __nv_bfloat162 h01 = __halves2bfloat162(hx, hy), h23 = __halves2bfloat162(hz, hw);
        __nv_bfloat162 l01 = __halves2bfloat162(lx, ly), l23 = __halves2bfloat162(lz, lw);
        ((uint2*)g_xhi)[i] = make_uint2(*(uint32_t*)&h01, *(uint32_t*)&h23);
        ((uint2*)g_xlo)[i] = make_uint2(*(uint32_t*)&l01, *(uint32_t*)&l23);
    }
}

__global__ void prep_weights(const float* __restrict__ Wq, const float* __restrict__ Wk,
                             const float* __restrict__ Wv, const float* __restrict__ Ws,
                             const float* __restrict__ bq, const float* __restrict__ bk,
                             const float* __restrict__ bv, const float* __restrict__ bs,
                             const float* __restrict__ We) {
    int idx = blockIdx.x * blockDim.x + threadIdx.x;
    if (idx < 512 * 256) {
        int col = idx / 256, k = idx % 256;
        int g = col / 128, n = col % 128;
        const float* W = (g == 0) ? Wq : (g == 1) ? Wk : (g == 2) ? Wv : Ws;
        float v = W[k * 128 + n];
        __nv_bfloat16 hi = __float2bfloat16(v);
        __nv_bfloat16 lo = __float2bfloat16(v - __bfloat162float(hi));
        g_WTh[col * 256 + k] = hi;
        g_WTl[col * 256 + k] = lo;
    }
    if (idx < 512) {
        const float* b = (idx < 128) ? bq : (idx < 256) ? bk : (idx < 384) ? bv : bs;
        g_bcat[idx] = b[idx % 128];
    }
    if (idx < 128 * 64) {
        int c = idx / 64, d = idx % 64;
        g_WeT[c * 64 + d] = We[d * 128 + c];
    }
    if (idx < 128) g_zero128[idx] = 0.f;
}

// ---------------- CSR build ---------------------------------------------------
__global__ void zero_deg_kernel() {
    int i = blockIdx.x * blockDim.x + threadIdx.x;
    if (i < N_NODES) g_deg[i] = 0;
}
__global__ void count_kernel(const int* __restrict__ edge_index) {
    int i = blockIdx.x * blockDim.x + threadIdx.x;
    if (i < N_EDGES) atomicAdd(&g_deg[clamp_node(edge_index[N_EDGES + i])], 1);
}
__global__ __launch_bounds__(256) void reduce_deg_kernel() {
    __shared__ int sm[256];
    int t = threadIdx.x;
    int i = blockIdx.x * 256 + t;
    sm[t] = (i < N_NODES) ? g_deg[i] : 0;
    __syncthreads();
#pragma unroll
    for (int s = 128; s > 0; s >>= 1) {
        if (t < s) sm[t] += sm[t + s];
        __syncthreads();
    }
    if (t == 0) g_part[blockIdx.x] = sm[0];
}
__global__ __launch_bounds__(256) void scan_parts_kernel() {
    __shared__ int sp[256];
    int t = threadIdx.x;
    int v = (t < SCAN_BLOCKS) ? g_part[t] : 0;
    sp[t] = v;
    __syncthreads();
#pragma unroll
    for (int off = 1; off < 256; off <<= 1) {
        int u = (t >= off) ? sp[t - off] : 0;
        __syncthreads();
        sp[t] += u;
        __syncthreads();
    }
    if (t < SCAN_BLOCKS) g_part[t] = sp[t] - v;
}
__global__ __launch_bounds__(256) void write_off_kernel() {
    __shared__ int sc[256];
    int t = threadIdx.x;
    int i = blockIdx.x * 256 + t;
    int d = (i < N_NODES) ? g_deg[i] : 0;
    sc[t] = d;
    __syncthreads();
#pragma unroll
    for (int off = 1; off < 256; off <<= 1) {
        int u = (t >= off) ? sc[t - off] : 0;
        __syncthreads();
        sc[t] += u;
        __syncthreads();
    }
    int excl = sc[t] - d + g_part[blockIdx.x];
    if (i < N_NODES) {
        g_off[i] = excl;
        g_cur[i] = excl;
        if (i == N_NODES - 1) g_off[N_NODES] = excl + d;
    }
}
__global__ void scatter_kernel(const int* __restrict__ edge_index) {
    int i = blockIdx.x * blockDim.x + threadIdx.x;
    if (i < N_EDGES) {
        int dst = clamp_node(edge_index[N_EDGES + i]);
        int p = atomicAdd(&g_cur[dst], 1);
        if (p >= 0 && p < N_EDGES) g_eorder[p] = i;
    }
}

// ---------------- fused attention ---------------------------------------------
__global__ __launch_bounds__(256) void attn_kernel(
    const int* __restrict__ edge_index, const float* __restrict__ edge_attr,
    const float* __restrict__ be)
{
    const int warp = threadIdx.x / 32;
    const int lane = threadIdx.x % 32;
    const int node = blockIdx.x * 8 + warp;
    if (node >= N_NODES) return;

    const float* prow = g_proj + (size_t)node * 512;
    const float4 qv = *(const float4*)(prow + lane * 4);
    const float2 qe = *(const float2*)(g_qe + (size_t)node * 64 + lane * 2);

    float4 accv = make_float4(0.f, 0.f, 0.f, 0.f);
    float2 acce = make_float2(0.f, 0.f);
    float m = -INFINITY;
    float s = 0.f;

    int beg = g_off[node];
    int end = g_off[node + 1];
    if (beg < 0) beg = 0;
    if (end > N_EDGES) end = N_EDGES;

    for (int p = beg; p < end; p++) {
        const int ei  = g_eorder[p];
        const int src = clamp_node(__ldg(&edge_index[ei]));

        const float* srow = g_proj + (size_t)src * 512;
        const float4 kv = *(const float4*)(srow + 128 + lane * 4);
        const float4 vv = *(const float4*)(srow + 256 + lane * 4);
        const float2 ea = *(const float2*)(edge_attr + (size_t)ei * 64 + lane * 2);

        float d = fmaf(qv.x, kv.x,
                  fmaf(qv.y, kv.y,
                  fmaf(qv.z, kv.z,
                  fmaf(qv.w, kv.w,
                  fmaf(qe.x, ea.x, qe.y * ea.y)))));
#pragma unroll
        for (int off = 16; off > 0; off >>= 1)
            d += __shfl_xor_sync(0xFFFFFFFFu, d, off);

        const float alpha = d * 0.08838834764831845f;   // 1/sqrt(128)
        const float nm = fmaxf(m, alpha);
        const float f  = __expf(m - nm);
        const float w  = __expf(alpha - nm);
        s = s * f + w;
        accv.x = fmaf(w, vv.x, accv.x * f);
        accv.y = fmaf(w, vv.y, accv.y * f);
        accv.z = fmaf(w, vv.z, accv.z * f);
        accv.w = fmaf(w, vv.w, accv.w * f);
        acce.x = fmaf(w, ea.x, acce.x * f);
        acce.y = fmaf(w, ea.y, acce.y * f);
        m = nm;
    }

    const float inv  = 1.0f / (s + 1e-16f);
    const float flag = (end > beg) ? 1.0f : 0.0f;
    const float4 bev = *(const float4*)(be + lane * 4);

    float4 ov;
    ov.x = fmaf(accv.x, inv, flag * bev.x);
    ov.y = fmaf(accv.y, inv, flag * bev.y);
    ov.z = fmaf(accv.z, inv, flag * bev.z);
    ov.w = fmaf(accv.w, inv, flag * bev.w);
    *(float4*)(g_aggv + (size_t)node * 128 + lane * 4) = ov;

    float2 oe;
    oe.x = acce.x * inv;
    oe.y = acce.y * inv;
    *(float2*)(g_agge + (size_t)node * 64 + lane * 2) = oe;
}

// ---------------- launch ------------------------------------------------------
extern "C" void kernel_launch(void* const* d_in, const int* in_sizes, int n_in,
                              void* d_out, int out_size)
{
    const float* x    = (const float*)d_in[0];
    const int*   eidx = (const int*)d_in[1];
    const float* ea   = (const float*)d_in[2];
    const float* Wq   = (const float*)d_in[3];
    const float* bq   = (const float*)d_in[4];
    const float* Wk   = (const float*)d_in[5];
    const float* bk   = (const float*)d_in[6];
    const float* Wv   = (const float*)d_in[7];
    const float* bv   = (const float*)d_in[8];
    const float* We   = (const float*)d_in[9];
    const float* be   = (const float*)d_in[10];
    const float* Ws   = (const float*)d_in[11];
    const float* bs   = (const float*)d_in[12];
    float*       out  = (float*)d_out;

    cudaFuncSetAttribute(gemm_mma, cudaFuncAttributeMaxDynamicSharedMemorySize, MMA_SMEM);

    float *dproj, *dqe, *daggv, *dagge, *dbcat, *dWeT, *dzero;
    __nv_bfloat16 *dxh, *dxl, *dWTh, *dWTl;
    cudaGetSymbolAddress((void**)&dproj, g_proj);
    cudaGetSymbolAddress((void**)&dqe,   g_qe);
    cudaGetSymbolAddress((void**)&daggv, g_aggv);
    cudaGetSymbolAddress((void**)&dagge, g_agge);
    cudaGetSymbolAddress((void**)&dbcat, g_bcat);
    cudaGetSymbolAddress((void**)&dWeT,  g_WeT);
    cudaGetSymbolAddress((void**)&dzero, g_zero128);
    cudaGetSymbolAddress((void**)&dxh,   g_xhi);
    cudaGetSymbolAddress((void**)&dxl,   g_xlo);
    cudaGetSymbolAddress((void**)&dWTh,  g_WTh);
    cudaGetSymbolAddress((void**)&dWTl,  g_WTl);

    // prep: weights + x hi/lo split
    prep_weights<<<(512 * 256 + 255) / 256, 256>>>(Wq, Wk, Wv, Ws, bq, bk, bv, bs, We);
    split_x_kernel<<<(N_NODES * IN_SIZE / 4 + 255) / 256, 256>>>(x);

    // CSR build
    zero_deg_kernel<<<(N_NODES + 255) / 256, 256>>>();
    count_kernel<<<(N_EDGES + 255) / 256, 256>>>(eidx);
    reduce_deg_kernel<<<SCAN_BLOCKS, 256>>>();
    scan_parts_kernel<<<1, 256>>>();
    write_off_kernel<<<SCAN_BLOCKS, 256>>>();
    scatter_kernel<<<(N_EDGES + 255) / 256, 256>>>(eidx);

    // node projections via bf16x3 tensor cores: proj = x @ Wcat + bcat
    {
        dim3 grid(4, (N_NODES + 127) / 128);
        gemm_mma<<<grid, 256, MMA_SMEM>>>(dxh, dxl, dWTh, dWTl, dbcat, dproj);
    }
    // qe[M,64] = q[M,128] @ WeT[128,64]
    {
        dim3 grid(1, (N_NODES + 127) / 128);
        sgemm_bias<128, 64, 8, 8, 4><<<grid, 256>>>(
            dproj, 512, dWeT, dzero, dqe,
            nullptr, 0, nullptr, 0, 0, N_NODES, 64, 128);
    }

    // fused attention: aggv, agge
    attn_kernel<<<(N_NODES + 7) / 8, 256>>>(eidx, ea, be);

    // out = agge[M,64] @ We[64,128] + aggv + skip, then ELU
    {
        dim3 grid(1, (N_NODES + 127) / 128);
        sgemm_bias<128, 128, 8, 8, 8><<<grid, 256>>>(
            dagge, EDGE_DIM, We, dzero, out,
            daggv, 128, dproj + 384, 512, 1, N_NODES, 128, 64);
    }
}

// round 8
// speedup vs baseline: 2.8465x; 1.0849x over previous
#include <cuda_runtime.h>
#include <cuda_bf16.h>
#include <math.h>
#include <stdint.h>

#define N_NODES 50000
#define N_EDGES 800000
#define IN_SIZE 256
#define OUT_SIZE 128
#define EDGE_DIM 64
#define SCAN_BLOCKS ((N_NODES + 255) / 256)   // 196

// ---------------- scratch (static device globals; no runtime allocation) ----
__device__ float g_proj[(size_t)N_NODES * 512];          // rows: [q|k|v|skip], stride 512
__device__ float g_qe[(size_t)N_NODES * EDGE_DIM];
__device__ float g_aggv[(size_t)N_NODES * OUT_SIZE];
__device__ float g_agge[(size_t)N_NODES * EDGE_DIM];
__device__ __nv_bfloat16 g_xhi[(size_t)N_NODES * IN_SIZE];
__device__ __nv_bfloat16 g_xlo[(size_t)N_NODES * IN_SIZE];
__device__ __nv_bfloat16 g_WTh[512 * 256];               // [n=512][k=256] = Wcat^T hi
__device__ __nv_bfloat16 g_WTl[512 * 256];
__device__ float g_bcat[512];
__device__ float g_WeT[128 * 64];                        // [K=128][N=64] = We^T
__device__ float g_zero128[128];
__device__ int   g_deg[N_NODES];
__device__ int   g_off[N_NODES + 1];
__device__ int   g_cur[N_NODES];
__device__ int   g_eorder[N_EDGES];
__device__ int   g_part[SCAN_BLOCKS];

__device__ __forceinline__ int clamp_node(int v) {
    return (v < 0) ? 0 : ((v >= N_NODES) ? N_NODES - 1 : v);
}
__device__ __forceinline__ uint32_t smem_u32(const void* p) {
    uint32_t a;
    asm("{ .reg .u64 t; cvta.to.shared.u64 t, %1; cvt.u32.u64 %0, t; }" : "=r"(a) : "l"(p));
    return a;
}

#define CPASYNC16(saddr, gptr) \
    asm volatile("cp.async.cg.shared.global [%0], [%1], 16;" :: "r"(saddr), "l"(gptr))
#define CP_COMMIT() asm volatile("cp.async.commit_group;" ::: "memory")
#define LDM4(d, addr) \
    asm volatile("ldmatrix.sync.aligned.m8n8.x4.shared.b16 {%0,%1,%2,%3}, [%4];" \
        : "=r"((d)[0]), "=r"((d)[1]), "=r"((d)[2]), "=r"((d)[3]) : "r"(addr))
#define MMA16816(c, a, b0v, b1v) \
    asm volatile("mma.sync.aligned.m16n8k16.row.col.f32.bf16.bf16.f32 " \
        "{%0,%1,%2,%3}, {%4,%5,%6,%7}, {%8,%9}, {%0,%1,%2,%3};" \
        : "+f"((c)[0]), "+f"((c)[1]), "+f"((c)[2]), "+f"((c)[3]) \
        : "r"((a)[0]), "r"((a)[1]), "r"((a)[2]), "r"((a)[3]), "r"(b0v), "r"(b1v))

// ---------------- bf16x3 tensor-core GEMM for node projections ---------------
#define NSTAGE 8            // 256 / 32
#define SROWB  80           // bytes per row slot (32 bf16 + 8 pad)
#define OFF_AH 0
#define OFF_AL 10240
#define OFF_BH 20480
#define OFF_BL 30720
#define BUFSZ  40960
#define MMA_SMEM (2 * BUFSZ)   // 81920

__global__ __launch_bounds__(256, 2) void gemm_mma(
    const __nv_bfloat16* __restrict__ Ahg, const __nv_bfloat16* __restrict__ Alg,
    const __nv_bfloat16* __restrict__ Bhg, const __nv_bfloat16* __restrict__ Blg,
    const float* __restrict__ bias, float* __restrict__ C)
{
    extern __shared__ char sm[];
    const uint32_t sb = smem_u32(sm);
    const int tid  = threadIdx.x;
    const int lane = tid & 31, wid = tid >> 5;
    const int wm = wid >> 1, wn = wid & 1;        // 4 x 2 warp grid
    const int row0 = blockIdx.y * 128;
    const int col0 = blockIdx.x * 128;

    float acc[2][8][4];
#pragma unroll
    for (int m = 0; m < 2; m++)
#pragma unroll
        for (int n = 0; n < 8; n++)
#pragma unroll
            for (int i = 0; i < 4; i++) acc[m][n][i] = 0.f;

    const int r8  = lane & 7, grp = lane >> 3;
    const int aRow = wm * 32 + ((grp & 1) << 3) + r8;
    const int aKel = (grp >> 1) << 3;
    const int bRow = wn * 64 + ((grp >> 1) << 3) + r8;
    const int bKel = (grp & 1) << 3;

#define LOAD_STAGE(s) do {                                                      \
        const int k0 = (s) * 32;                                                \
        const uint32_t bb = sb + ((s) & 1) * BUFSZ;                             \
        _Pragma("unroll")                                                       \
        for (int c = 0; c < 2; c++) {                                           \
            int idx = tid * 2 + c;                                              \
            int row = idx >> 2, sub = idx & 3;                                  \
            int gr = row0 + row; if (gr >= N_NODES) gr = N_NODES - 1;           \
            size_t gaoff = (size_t)gr * IN_SIZE + k0 + sub * 8;                 \
            uint32_t soff = row * SROWB + sub * 16;                             \
            CPASYNC16(bb + OFF_AH + soff, Ahg + gaoff);                         \
            CPASYNC16(bb + OFF_AL + soff, Alg + gaoff);                         \
            size_t gboff = (size_t)(col0 + row) * IN_SIZE + k0 + sub * 8;       \
            CPASYNC16(bb + OFF_BH + soff, Bhg + gboff);                         \
            CPASYNC16(bb + OFF_BL + soff, Blg + gboff);                         \
        }                                                                       \
        CP_COMMIT();                                                            \
    } while (0)

    LOAD_STAGE(0);

    for (int s = 0; s < NSTAGE; s++) {
        if (s + 1 < NSTAGE) {
            LOAD_STAGE(s + 1);
            asm volatile("cp.async.wait_group 1;" ::: "memory");
        } else {
            asm volatile("cp.async.wait_group 0;" ::: "memory");
        }
        __syncthreads();

        const uint32_t bb = sb + (s & 1) * BUFSZ;
#pragma unroll
        for (int ks = 0; ks < 32; ks += 16) {
            uint32_t ah[2][4], al[2][4];
#pragma unroll
            for (int mt = 0; mt < 2; mt++) {
                uint32_t ad = bb + OFF_AH + (aRow + mt * 16) * SROWB + (aKel + ks) * 2;
                LDM4(ah[mt], ad);
                LDM4(al[mt], ad + (OFF_AL - OFF_AH));
            }
#pragma unroll
            for (int p = 0; p < 4; p++) {
                uint32_t bh[4], bl[4];
                uint32_t bd = bb + OFF_BH + (bRow + p * 16) * SROWB + (bKel + ks) * 2;
                LDM4(bh, bd);
                LDM4(bl, bd + (OFF_BL - OFF_BH));
#pragma unroll
                for (int mt = 0; mt < 2; mt++) {
#pragma unroll
                    for (int t = 0; t < 2; t++) {
                        float* cc = acc[mt][p * 2 + t];
                        MMA16816(cc, ah[mt], bh[2 * t], bh[2 * t + 1]);
                        MMA16816(cc, ah[mt], bl[2 * t], bl[2 * t + 1]);
                        MMA16816(cc, al[mt], bh[2 * t], bh[2 * t + 1]);
                    }
                }
            }
        }
        __syncthreads();
    }

#pragma unroll
    for (int mt = 0; mt < 2; mt++) {
        int r = row0 + wm * 32 + mt * 16 + (lane >> 2);
#pragma unroll
        for (int p = 0; p < 8; p++) {
            int col = col0 + wn * 64 + p * 8 + (lane & 3) * 2;
            float b0 = __ldg(bias + col), b1 = __ldg(bias + col + 1);
            if (r < N_NODES) {
                float2 o = make_float2(acc[mt][p][0] + b0, acc[mt][p][1] + b1);
                *(float2*)(C + (size_t)r * 512 + col) = o;
            }
            if (r + 8 < N_NODES) {
                float2 o = make_float2(acc[mt][p][2] + b0, acc[mt][p][3] + b1);
                *(float2*)(C + (size_t)(r + 8) * 512 + col) = o;
            }
        }
    }
#undef LOAD_STAGE
}

// ---------------- fp32 double-buffered SGEMM (small GEMMs) --------------------
template <int BM, int BN, int BK, int TM, int TN>
__global__ __launch_bounds__(256) void sgemm_bias(
    const float* __restrict__ A, int lda,
    const float* __restrict__ B,
    const float* __restrict__ bias, float* __restrict__ C,
    const float* __restrict__ add1, int as1,
    const float* __restrict__ add2, int as2,
    int do_elu, int M, int N, int K)
{
    static_assert(TN % 4 == 0, "float4 epilogue requires TN % 4 == 0");
    static_assert(TM * TN * 256 == BM * BN, "thread tile mismatch");

    __shared__ float As[2][BK][BM];
    __shared__ float Bs[2][BK][BN];

    const int tid  = threadIdx.x;
    const int row0 = blockIdx.y * BM;
    const int col0 = blockIdx.x * BN;

    const int tRow = (tid / (BN / TN)) * TM;
    const int tCol = (tid % (BN / TN)) * TN;

    const int aRow = tid / (BK / 4);
    const int aCol = (tid % (BK / 4)) * 4;
    const int bRow = tid / (BN / 4);
    const int bCol = (tid % (BN / 4)) * 4;

    float acc[TM][TN];
#pragma unroll
    for (int i = 0; i < TM; i++)
#pragma unroll
        for (int j = 0; j < TN; j++) acc[i][j] = 0.0f;

    {
        float4 av = make_float4(0.f, 0.f, 0.f, 0.f);
        if (row0 + aRow < M)
            av = *(const float4*)(A + (size_t)(row0 + aRow) * lda + aCol);
        As[0][aCol + 0][aRow] = av.x;
        As[0][aCol + 1][aRow] = av.y;
        As[0][aCol + 2][aRow] = av.z;
        As[0][aCol + 3][aRow] = av.w;
        if (bRow < BK)
            *(float4*)&Bs[0][bRow][bCol] = *(const float4*)(B + (size_t)bRow * N + col0 + bCol);
    }
    __syncthreads();

    int buf = 0;
    for (int k0 = BK; k0 < K + BK; k0 += BK) {
        const bool has = (k0 < K);
        float4 aNext = make_float4(0.f, 0.f, 0.f, 0.f);
        float4 bNext;
        if (has) {
            if (row0 + aRow < M)
                aNext = *(const float4*)(A + (size_t)(row0 + aRow) * lda + k0 + aCol);
            if (bRow < BK)
                bNext = *(const float4*)(B + (size_t)(k0 + bRow) * N + col0 + bCol);
        }

        float regM[TM], regN[TN];
#pragma unroll
        for (int kk = 0; kk < BK; kk++) {
#pragma unroll
            for (int i = 0; i < TM; i++) regM[i] = As[buf][kk][tRow + i];
#pragma unroll
            for (int j = 0; j < TN; j++) regN[j] = Bs[buf][kk][tCol + j];
#pragma unroll
            for (int i = 0; i < TM; i++)
#pragma unroll
                for (int j = 0; j < TN; j++)
                    acc[i][j] = fmaf(regM[i], regN[j], acc[i][j]);
        }

        if (has) {
            const int nb = buf ^ 1;
            As[nb][aCol + 0][aRow] = aNext.x;
            As[nb][aCol + 1][aRow] = aNext.y;
            As[nb][aCol + 2][aRow] = aNext.z;
            As[nb][aCol + 3][aRow] = aNext.w;
            if (bRow < BK)
                *(float4*)&Bs[nb][bRow][bCol] = bNext;
            __syncthreads();
            buf = nb;
        }
    }

#pragma unroll
    for (int i = 0; i < TM; i++) {
        int r = row0 + tRow + i;
        if (r >= M) continue;
#pragma unroll
        for (int j = 0; j < TN; j += 4) {
            int c = col0 + tCol + j;
            float4 o;
            o.x = acc[i][j + 0] + bias[c + 0];
            o.y = acc[i][j + 1] + bias[c + 1];
            o.z = acc[i][j + 2] + bias[c + 2];
            o.w = acc[i][j + 3] + bias[c + 3];
            if (add1) {
                float4 a1 = *(const float4*)(add1 + (size_t)r * as1 + c);
                o.x += a1.x; o.y += a1.y; o.z += a1.z; o.w += a1.w;
            }
            if (add2) {
                float4 a2 = *(const float4*)(add2 + (size_t)r * as2 + c);
                o.x += a2.x; o.y += a2.y; o.z += a2.z; o.w += a2.w;
            }
            if (do_elu) {
                o.x = (o.x > 0.f) ? o.x : expm1f(o.x);
                o.y = (o.y > 0.f) ? o.y : expm1f(o.y);
                o.z = (o.z > 0.f) ? o.z : expm1f(o.z);
                o.w = (o.w > 0.f) ? o.w : expm1f(o.w);
            }
            *(float4*)(C + (size_t)r * N + c) = o;
        }
    }
}

// ---------------- prep kernels ------------------------------------------------
__global__ void split_x_kernel(const float* __restrict__ x) {
    int i = blockIdx.x * blockDim.x + threadIdx.x;
    if (i < N_NODES * IN_SIZE / 4) {
        float4 v = ((const float4*)x)[i];
        __nv_bfloat16 hx = __float2bfloat16(v.x), hy = __float2bfloat16(v.y);
        __nv_bfloat16 hz = __float2bfloat16(v.z), hw = __float2bfloat16(v.w);
        __nv_bfloat16 lx = __float2bfloat16(v.x - __bfloat162float(hx));
        __nv_bfloat16 ly = __float2bfloat16(v.y - __bfloat162float(hy));
        __nv_bfloat16 lz = __float2bfloat16(v.z - __bfloat162float(hz));
        __nv_bfloat16 lw = __float2bfloat16(v.w - __bfloat162float(hw));
        __nv_bfloat162 h01 = __halves2bfloat162(hx, hy), h23 = __halves2bfloat162(hz, hw);
        __nv_bfloat162 l01 = __halves2bfloat162(lx, ly), l23 = __halves2bfloat162(lz, lw);
        ((uint2*)g_xhi)[i] = make_uint2(*(uint32_t*)&h01, *(uint32_t*)&h23);
        ((uint2*)g_xlo)[i] = make_uint2(*(uint32_t*)&l01, *(uint32_t*)&l23);
    }
}

__global__ void prep_weights(const float* __restrict__ Wq, const float* __restrict__ Wk,
                             const float* __restrict__ Wv, const float* __restrict__ Ws,
                             const float* __restrict__ bq, const float* __restrict__ bk,
                             const float* __restrict__ bv, const float* __restrict__ bs,
                             const float* __restrict__ We) {
    int idx = blockIdx.x * blockDim.x + threadIdx.x;
    if (idx < 512 * 256) {
        int col = idx / 256, k = idx % 256;
        int g = col / 128, n = col % 128;
        const float* W = (g == 0) ? Wq : (g == 1) ? Wk : (g == 2) ? Wv : Ws;
        float v = W[k * 128 + n];
        __nv_bfloat16 hi = __float2bfloat16(v);
        __nv_bfloat16 lo = __float2bfloat16(v - __bfloat162float(hi));
        g_WTh[col * 256 + k] = hi;
        g_WTl[col * 256 + k] = lo;
    }
    if (idx < 512) {
        const float* b = (idx < 128) ? bq : (idx < 256) ? bk : (idx < 384) ? bv : bs;
        g_bcat[idx] = b[idx % 128];
    }
    if (idx < 128 * 64) {
        int c = idx / 64, d = idx % 64;
        g_WeT[c * 64 + d] = We[d * 128 + c];
    }
    if (idx < 128) g_zero128[idx] = 0.f;
}

// ---------------- CSR build ---------------------------------------------------
__global__ void zero_deg_kernel() {
    int i = blockIdx.x * blockDim.x + threadIdx.x;
    if (i < N_NODES) g_deg[i] = 0;
}
__global__ void count_kernel(const int* __restrict__ edge_index) {
    int i = blockIdx.x * blockDim.x + threadIdx.x;
    if (i < N_EDGES) atomicAdd(&g_deg[clamp_node(edge_index[N_EDGES + i])], 1);
}
__global__ __launch_bounds__(256) void reduce_deg_kernel() {
    __shared__ int sm[256];
    int t = threadIdx.x;
    int i = blockIdx.x * 256 + t;
    sm[t] = (i < N_NODES) ? g_deg[i] : 0;
    __syncthreads();
#pragma unroll
    for (int s = 128; s > 0; s >>= 1) {
        if (t < s) sm[t] += sm[t + s];
        __syncthreads();
    }
    if (t == 0) g_part[blockIdx.x] = sm[0];
}
__global__ __launch_bounds__(256) void scan_parts_kernel() {
    __shared__ int sp[256];
    int t = threadIdx.x;
    int v = (t < SCAN_BLOCKS) ? g_part[t] : 0;
    sp[t] = v;
    __syncthreads();
#pragma unroll
    for (int off = 1; off < 256; off <<= 1) {
        int u = (t >= off) ? sp[t - off] : 0;
        __syncthreads();
        sp[t] += u;
        __syncthreads();
    }
    if (t < SCAN_BLOCKS) g_part[t] = sp[t] - v;
}
__global__ __launch_bounds__(256) void write_off_kernel() {
    __shared__ int sc[256];
    int t = threadIdx.x;
    int i = blockIdx.x * 256 + t;
    int d = (i < N_NODES) ? g_deg[i] : 0;
    sc[t] = d;
    __syncthreads();
#pragma unroll
    for (int off = 1; off < 256; off <<= 1) {
        int u = (t >= off) ? sc[t - off] : 0;
        __syncthreads();
        sc[t] += u;
        __syncthreads();
    }
    int excl = sc[t] - d + g_part[blockIdx.x];
    if (i < N_NODES) {
        g_off[i] = excl;
        g_cur[i] = excl;
        if (i == N_NODES - 1) g_off[N_NODES] = excl + d;
    }
}
__global__ void scatter_kernel(const int* __restrict__ edge_index) {
    int i = blockIdx.x * blockDim.x + threadIdx.x;
    if (i < N_EDGES) {
        int dst = clamp_node(edge_index[N_EDGES + i]);
        int p = atomicAdd(&g_cur[dst], 1);
        if (p >= 0 && p < N_EDGES) g_eorder[p] = i;
    }
}

// ---------------- fused attention (2-edge pipelined) --------------------------
__global__ __launch_bounds__(256) void attn_kernel(
    const int* __restrict__ edge_index, const float* __restrict__ edge_attr,
    const float* __restrict__ be)
{
    const int warp = threadIdx.x / 32;
    const int lane = threadIdx.x % 32;
    const int node = blockIdx.x * 8 + warp;
    if (node >= N_NODES) return;

    const float* prow = g_proj + (size_t)node * 512;
    const float4 qv = __ldg((const float4*)(prow + lane * 4));
    const float2 qe = __ldg((const float2*)(g_qe + (size_t)node * 64 + lane * 2));

    float4 accv = make_float4(0.f, 0.f, 0.f, 0.f);
    float2 acce = make_float2(0.f, 0.f);
    float m = -INFINITY;
    float s = 0.f;

    int beg = g_off[node];
    int end = g_off[node + 1];
    if (beg < 0) beg = 0;
    if (end > N_EDGES) end = N_EDGES;

    int p = beg;
    for (; p + 1 < end; p += 2) {
        const int ei0  = __ldg(&g_eorder[p]);
        const int ei1  = __ldg(&g_eorder[p + 1]);
        const int src0 = clamp_node(__ldg(&edge_index[ei0]));
        const int src1 = clamp_node(__ldg(&edge_index[ei1]));

        const float* s0 = g_proj + (size_t)src0 * 512;
        const float* s1 = g_proj + (size_t)src1 * 512;
        const float4 kv0 = __ldg((const float4*)(s0 + 128 + lane * 4));
        const float4 kv1 = __ldg((const float4*)(s1 + 128 + lane * 4));
        const float4 vv0 = __ldg((const float4*)(s0 + 256 + lane * 4));
        const float4 vv1 = __ldg((const float4*)(s1 + 256 + lane * 4));
        const float2 ea0 = __ldg((const float2*)(edge_attr + (size_t)ei0 * 64 + lane * 2));
        const float2 ea1 = __ldg((const float2*)(edge_attr + (size_t)ei1 * 64 + lane * 2));

        float d0 = fmaf(qv.x, kv0.x, fmaf(qv.y, kv0.y, fmaf(qv.z, kv0.z,
                   fmaf(qv.w, kv0.w, fmaf(qe.x, ea0.x, qe.y * ea0.y)))));
        float d1 = fmaf(qv.x, kv1.x, fmaf(qv.y, kv1.y, fmaf(qv.z, kv1.z,
                   fmaf(qv.w, kv1.w, fmaf(qe.x, ea1.x, qe.y * ea1.y)))));
#pragma unroll
        for (int off = 16; off > 0; off >>= 1) {
            d0 += __shfl_xor_sync(0xFFFFFFFFu, d0, off);
            d1 += __shfl_xor_sync(0xFFFFFFFFu, d1, off);
        }

        const float a0 = d0 * 0.08838834764831845f;   // 1/sqrt(128)
        const float a1 = d1 * 0.08838834764831845f;
        const float nm = fmaxf(m, fmaxf(a0, a1));
        const float f  = __expf(m - nm);              // 0 on first pair (m = -inf)
        const float w0 = __expf(a0 - nm);
        const float w1 = __expf(a1 - nm);
        s = s * f + w0 + w1;
        accv.x = fmaf(w1, vv1.x, fmaf(w0, vv0.x, accv.x * f));
        accv.y = fmaf(w1, vv1.y, fmaf(w0, vv0.y, accv.y * f));
        accv.z = fmaf(w1, vv1.z, fmaf(w0, vv0.z, accv.z * f));
        accv.w = fmaf(w1, vv1.w, fmaf(w0, vv0.w, accv.w * f));
        acce.x = fmaf(w1, ea1.x, fmaf(w0, ea0.x, acce.x * f));
        acce.y = fmaf(w1, ea1.y, fmaf(w0, ea0.y, acce.y * f));
        m = nm;
    }
    if (p < end) {
        const int ei  = __ldg(&g_eorder[p]);
        const int src = clamp_node(__ldg(&edge_index[ei]));
        const float* s0 = g_proj + (size_t)src * 512;
        const float4 kv = __ldg((const float4*)(s0 + 128 + lane * 4));
        const float4 vv = __ldg((const float4*)(s0 + 256 + lane * 4));
        const float2 ea = __ldg((const float2*)(edge_attr + (size_t)ei * 64 + lane * 2));

        float d = fmaf(qv.x, kv.x, fmaf(qv.y, kv.y, fmaf(qv.z, kv.z,
                  fmaf(qv.w, kv.w, fmaf(qe.x, ea.x, qe.y * ea.y)))));
#pragma unroll
        for (int off = 16; off > 0; off >>= 1)
            d += __shfl_xor_sync(0xFFFFFFFFu, d, off);

        const float alpha = d * 0.08838834764831845f;
        const float nm = fmaxf(m, alpha);
        const float f  = __expf(m - nm);
        const float w  = __expf(alpha - nm);
        s = s * f + w;
        accv.x = fmaf(w, vv.x, accv.x * f);
        accv.y = fmaf(w, vv.y, accv.y * f);
        accv.z = fmaf(w, vv.z, accv.z * f);
        accv.w = fmaf(w, vv.w, accv.w * f);
        acce.x = fmaf(w, ea.x, acce.x * f);
        acce.y = fmaf(w, ea.y, acce.y * f);
        m = nm;
    }

    const float inv  = 1.0f / (s + 1e-16f);
    const float flag = (end > beg) ? 1.0f : 0.0f;
    const float4 bev = __ldg((const float4*)(be + lane * 4));

    float4 ov;
    ov.x = fmaf(accv.x, inv, flag * bev.x);
    ov.y = fmaf(accv.y, inv, flag * bev.y);
    ov.z = fmaf(accv.z, inv, flag * bev.z);
    ov.w = fmaf(accv.w, inv, flag * bev.w);
    *(float4*)(g_aggv + (size_t)node * 128 + lane * 4) = ov;

    float2 oe;
    oe.x = acce.x * inv;
    oe.y = acce.y * inv;
    *(float2*)(g_agge + (size_t)node * 64 + lane * 2) = oe;
}

// ---------------- launch ------------------------------------------------------
extern "C" void kernel_launch(void* const* d_in, const int* in_sizes, int n_in,
                              void* d_out, int out_size)
{
    const float* x    = (const float*)d_in[0];
    const int*   eidx = (const int*)d_in[1];
    const float* ea   = (const float*)d_in[2];
    const float* Wq   = (const float*)d_in[3];
    const float* bq   = (const float*)d_in[4];
    const float* Wk   = (const float*)d_in[5];
    const float* bk   = (const float*)d_in[6];
    const float* Wv   = (const float*)d_in[7];
    const float* bv   = (const float*)d_in[8];
    const float* We   = (const float*)d_in[9];
    const float* be   = (const float*)d_in[10];
    const float* Ws   = (const float*)d_in[11];
    const float* bs   = (const float*)d_in[12];
    float*       out  = (float*)d_out;

    cudaFuncSetAttribute(gemm_mma, cudaFuncAttributeMaxDynamicSharedMemorySize, MMA_SMEM);

    float *dproj, *dqe, *daggv, *dagge, *dbcat, *dWeT, *dzero;
    __nv_bfloat16 *dxh, *dxl, *dWTh, *dWTl;
    cudaGetSymbolAddress((void**)&dproj, g_proj);
    cudaGetSymbolAddress((void**)&dqe,   g_qe);
    cudaGetSymbolAddress((void**)&daggv, g_aggv);
    cudaGetSymbolAddress((void**)&dagge, g_agge);
    cudaGetSymbolAddress((void**)&dbcat, g_bcat);
    cudaGetSymbolAddress((void**)&dWeT,  g_WeT);
    cudaGetSymbolAddress((void**)&dzero, g_zero128);
    cudaGetSymbolAddress((void**)&dxh,   g_xhi);
    cudaGetSymbolAddress((void**)&dxl,   g_xlo);
    cudaGetSymbolAddress((void**)&dWTh,  g_WTh);
    cudaGetSymbolAddress((void**)&dWTl,  g_WTl);

    // launch order arranged so gemm_mma is launch index 3 (profiled slot)
    prep_weights<<<(512 * 256 + 255) / 256, 256>>>(Wq, Wk, Wv, Ws, bq, bk, bv, bs, We);  // 0
    split_x_kernel<<<(N_NODES * IN_SIZE / 4 + 255) / 256, 256>>>(x);                     // 1
    zero_deg_kernel<<<(N_NODES + 255) / 256, 256>>>();                                   // 2
    {
        dim3 grid(4, (N_NODES + 127) / 128);
        gemm_mma<<<grid, 256, MMA_SMEM>>>(dxh, dxl, dWTh, dWTl, dbcat, dproj);           // 3
    }
    count_kernel<<<(N_EDGES + 255) / 256, 256>>>(eidx);                                  // 4
    reduce_deg_kernel<<<SCAN_BLOCKS, 256>>>();                                           // 5
    scan_parts_kernel<<<1, 256>>>();                                                     // 6
    write_off_kernel<<<SCAN_BLOCKS, 256>>>();                                            // 7
    scatter_kernel<<<(N_EDGES + 255) / 256, 256>>>(eidx);                                // 8
    {
        dim3 grid(1, (N_NODES + 127) / 128);
        sgemm_bias<128, 64, 8, 8, 4><<<grid, 256>>>(
            dproj, 512, dWeT, dzero, dqe,
            nullptr, 0, nullptr, 0, 0, N_NODES, 64, 128);                                // 9
    }
    attn_kernel<<<(N_NODES + 7) / 8, 256>>>(eidx, ea, be);                               // 10
    {
        dim3 grid(1, (N_NODES + 127) / 128);
        sgemm_bias<128, 128, 8, 8, 8><<<grid, 256>>>(
            dagge, EDGE_DIM, We, dzero, out,
            daggv, 128, dproj + 384, 512, 1, N_NODES, 128, 64);                          // 11
    }
}